// round 2
// baseline (speedup 1.0000x reference)
#include <cuda_runtime.h>
#include <cstdint>

#define K_CODES 1024
#define DIM     256
#define T_LEN   4096
#define B_SZ    16
#define N_ROWS  (B_SZ * T_LEN)          // 65536
#define QN      ((size_t)B_SZ * DIM * T_LEN)  // 16777216

#define TM 64
#define TN 64
#define DC 64
#define NSTEPS ((K_CODES / TN) * (DIM / DC))  // 64
#define THREADS 256

// Normalized embeddings, transposed to [D][K] so B-tiles stream coalesced.
__device__ float g_enT[DIM * K_CODES];

__device__ __forceinline__ void cp16(uint32_t dst, const void* src) {
    asm volatile("cp.async.cg.shared.global [%0], [%1], 16;\n" :: "r"(dst), "l"(src));
}
__device__ __forceinline__ void cp_commit() {
    asm volatile("cp.async.commit_group;\n");
}
__device__ __forceinline__ void cp_wait1() {
    asm volatile("cp.async.wait_group 1;\n");
}
__device__ __forceinline__ void cp_wait0() {
    asm volatile("cp.async.wait_group 0;\n");
}

// ---------------------------------------------------------------------------
// Kernel A: L2-normalize embeddings, write transposed g_enT[d*K + k].
// Also zeroes the loss slot in d_out.
// ---------------------------------------------------------------------------
__global__ void vq_norm_kernel(const float* __restrict__ emb,
                               float* __restrict__ out, long long out_size) {
    int k = blockIdx.x;
    int d = threadIdx.x;   // 256 threads, one per dim
    float v = emb[(size_t)k * DIM + d];
    float s = v * v;
    #pragma unroll
    for (int o = 16; o; o >>= 1) s += __shfl_xor_sync(0xFFFFFFFFu, s, o);
    __shared__ float ws[8];
    __shared__ float rs_sh;
    if ((d & 31) == 0) ws[d >> 5] = s;
    __syncthreads();
    if (d == 0) {
        float t = 0.f;
        #pragma unroll
        for (int i = 0; i < 8; i++) t += ws[i];
        float n = sqrtf(t);
        rs_sh = 1.0f / fmaxf(n, 1e-12f);
        if (k == 0 && out_size > (long long)QN) out[QN] = 0.0f;  // zero loss slot
    }
    __syncthreads();
    g_enT[(size_t)d * K_CODES + k] = v * rs_sh;
}

// ---------------------------------------------------------------------------
// Kernel B: fused GEMM (x · enT) + running argmax + gather + loss + writeback.
// One block = 64 consecutive rows (n = b*T + t), all 1024 codes.
// smem: xs[DIM][TM] (x tile, full depth)  +  es[2][DC][TN] (double-buffered
// normalized-embedding chunks via cp.async). es region reused as reduction
// scratch after the mainloop.
// ---------------------------------------------------------------------------
__global__ void __launch_bounds__(THREADS, 2) vq_main_kernel(
    const float* __restrict__ x, const float* __restrict__ emb,
    float* __restrict__ out, long long out_size)
{
    extern __shared__ float smem[];
    float* xs = smem;                       // DIM*TM = 16384 floats
    float* es = smem + DIM * TM;            // 2*DC*TN = 8192 floats

    const int tid = threadIdx.x;
    const int tx  = tid & 15;               // col group (4 cols)
    const int ty  = tid >> 4;               // row group (4 rows)

    const int n0 = blockIdx.x * TM;         // first flat row (= b*T + t)
    const int b  = n0 / T_LEN;
    const int tl = n0 % T_LEN;              // multiple of 64 -> single batch
    const float* xb = x + (size_t)b * DIM * T_LEN + tl;

    const uint32_t es_base = (uint32_t)__cvta_generic_to_shared(es);

    // Prefetch chunk for step s into buffer buf: es[buf][kk][col] <-
    // g_enT[(dc*DC+kk)*K + cc*TN + col]
    auto load_chunk = [&](int s, int buf) {
        int cc = s >> 2, dc = s & 3;
        const float* src0 = g_enT + (size_t)(dc * DC) * K_CODES + cc * TN;
        uint32_t db = es_base + (uint32_t)buf * (DC * TN * 4);
        #pragma unroll
        for (int i = 0; i < 4; i++) {
            int lin = i * THREADS + tid;    // 0..1023
            int kk  = lin >> 4;
            int c4  = (lin & 15) << 2;
            cp16(db + (uint32_t)(kk * TN + c4) * 4, src0 + (size_t)kk * K_CODES + c4);
        }
        cp_commit();
    };

    // Kick off first embedding chunk, then load the x tile (coalesced along t).
    load_chunk(0, 0);
    #pragma unroll
    for (int i = 0; i < 16; i++) {
        int lin = i * THREADS + tid;        // 0..4095 float4s
        int d   = lin >> 4;
        int r4  = (lin & 15) << 2;
        float4 v = *(const float4*)(xb + (size_t)d * T_LEN + r4);
        *(float4*)(xs + d * TM + r4) = v;
    }
    __syncthreads();

    float cmax[4] = {-1e30f, -1e30f, -1e30f, -1e30f};
    int   cidx[4] = {0, 0, 0, 0};

    int step = 0;
    #pragma unroll 1
    for (int cc = 0; cc < K_CODES / TN; ++cc) {
        float acc[4][4];
        #pragma unroll
        for (int r = 0; r < 4; r++)
            #pragma unroll
            for (int j = 0; j < 4; j++) acc[r][j] = 0.f;

        #pragma unroll 1
        for (int dc = 0; dc < DIM / DC; ++dc, ++step) {
            int buf = step & 1;
            if (step + 1 < NSTEPS) { load_chunk(step + 1, buf ^ 1); cp_wait1(); }
            else                   { cp_wait0(); }
            __syncthreads();

            const float* ebuf = es + buf * (DC * TN);
            const float* xss  = xs + dc * DC * TM;
            #pragma unroll
            for (int kk = 0; kk < DC; ++kk) {
                float4 av = *(const float4*)(xss + kk * TM + (ty << 2));
                float4 bv = *(const float4*)(ebuf + kk * TN + (tx << 2));
                float ar[4] = {av.x, av.y, av.z, av.w};
                float br[4] = {bv.x, bv.y, bv.z, bv.w};
                #pragma unroll
                for (int r = 0; r < 4; r++)
                    #pragma unroll
                    for (int j = 0; j < 4; j++)
                        acc[r][j] = fmaf(ar[r], br[j], acc[r][j]);
            }
            __syncthreads();
        }

        int cbase = cc * TN + (tx << 2);
        #pragma unroll
        for (int r = 0; r < 4; r++)
            #pragma unroll
            for (int j = 0; j < 4; j++)
                if (acc[r][j] > cmax[r]) { cmax[r] = acc[r][j]; cidx[r] = cbase + j; }
    }

    // ---- cross-thread argmax reduce (reuse es region as scratch) ----
    float* redv  = es;                        // [TM][16]
    int*   redi  = (int*)(es + TM * 16);      // [TM][16]
    int*   idx_s = (int*)(es + TM * 16 * 2);  // [TM]
    #pragma unroll
    for (int r = 0; r < 4; r++) {
        redv[(ty * 4 + r) * 16 + tx] = cmax[r];
        redi[(ty * 4 + r) * 16 + tx] = cidx[r];
    }
    __syncthreads();
    if (tid < TM) {
        float bv = redv[tid * 16];
        int   bi = redi[tid * 16];
        #pragma unroll
        for (int j = 1; j < 16; j++) {
            float v = redv[tid * 16 + j];
            int   ix = redi[tid * 16 + j];
            if (v > bv || (v == bv && ix < bi)) { bv = v; bi = ix; }
        }
        idx_s[tid] = bi;
        if (out_size >= (long long)(QN + 1 + N_ROWS))
            out[QN + 1 + n0 + tid] = (float)bi;   // indices as f32
    }
    __syncthreads();

    // ---- epilogue: gather embedding row, write [B,D,T] coalesced, loss ----
    const int r    = tid & 63;    // local row (t)
    const int dsub = tid >> 6;    // quarter of D handled by this thread
    const int myidx = idx_s[r];
    const float4* erow4 = (const float4*)(emb + (size_t)myidx * DIM + dsub * 64);
    float* ob = out + (size_t)b * DIM * T_LEN + tl + r;
    float lsum = 0.f;
    #pragma unroll
    for (int dj = 0; dj < 16; ++dj) {
        float4 e4 = erow4[dj];               // contiguous per-thread -> L1-friendly
        int d = dsub * 64 + dj * 4;
        float ev[4] = {e4.x, e4.y, e4.z, e4.w};
        #pragma unroll
        for (int i = 0; i < 4; i++) {
            float xv = xs[(d + i) * TM + r];
            float df = ev[i] - xv;
            lsum = fmaf(df, df, lsum);
            ob[(size_t)(d + i) * T_LEN] = ev[i];   // 32 consecutive t per warp
        }
    }

    // ---- loss block-reduce + single atomic per block ----
    #pragma unroll
    for (int o = 16; o; o >>= 1) lsum += __shfl_xor_sync(0xFFFFFFFFu, lsum, o);
    __shared__ float wsum[8];
    if ((tid & 31) == 0) wsum[tid >> 5] = lsum;
    __syncthreads();
    if (tid == 0) {
        float t = 0.f;
        #pragma unroll
        for (int i = 0; i < 8; i++) t += wsum[i];
        if (out_size > (long long)QN)
            atomicAdd(out + QN, t * (1.25f / 16777216.0f));
    }
}

// ---------------------------------------------------------------------------
extern "C" void kernel_launch(void* const* d_in, const int* in_sizes, int n_in,
                              void* d_out, int out_size) {
    const float* x   = (const float*)d_in[0];
    const float* emb = (const float*)d_in[1];
    // Defensive: if input order is swapped, fix it (embeddings = 262144 elems).
    if (n_in >= 2 && in_sizes[0] == K_CODES * DIM && in_sizes[1] == (int)QN) {
        const float* t = x; x = emb; emb = t;
    }
    float* out = (float*)d_out;

    const int smem_bytes = (DIM * TM + 2 * DC * TN) * 4;  // 98304
    cudaFuncSetAttribute(vq_main_kernel,
                         cudaFuncAttributeMaxDynamicSharedMemorySize, smem_bytes);

    vq_norm_kernel<<<K_CODES, 256>>>(emb, out, (long long)out_size);
    vq_main_kernel<<<N_ROWS / TM, THREADS, smem_bytes>>>(x, emb, out, (long long)out_size);
}

// round 3
// speedup vs baseline: 1.0349x; 1.0349x over previous
#include <cuda_runtime.h>
#include <cstdint>

#define K_CODES 1024
#define DIM     256
#define T_LEN   4096
#define B_SZ    16
#define N_ROWS  (B_SZ * T_LEN)                 // 65536
#define QN      ((size_t)B_SZ * DIM * T_LEN)   // 16777216

#define TM 128
#define TN 128
#define DC 32
#define NSTEPS ((K_CODES / TN) * (DIM / DC))   // 64
#define THREADS 256
#define XS_F (TM * DIM)          // 32768 floats (x tile, [d][row])
#define EB_F (DC * TN)           // 4096 floats per stage
#define NSTAGE 3

// Normalized embeddings, transposed to [D][K] so B-tiles stream coalesced.
__device__ float g_enT[DIM * K_CODES];

__device__ __forceinline__ void cp16(uint32_t dst, const void* src) {
    asm volatile("cp.async.cg.shared.global [%0], [%1], 16;\n" :: "r"(dst), "l"(src));
}
__device__ __forceinline__ void cp_commit() {
    asm volatile("cp.async.commit_group;\n");
}
__device__ __forceinline__ void cp_wait1() {
    asm volatile("cp.async.wait_group 1;\n");
}
__device__ __forceinline__ void cp_wait0() {
    asm volatile("cp.async.wait_group 0;\n");
}

// ---------------------------------------------------------------------------
// Kernel A: L2-normalize embeddings, write transposed g_enT[d*K + k].
// Also zeroes the loss slot in d_out.
// ---------------------------------------------------------------------------
__global__ void vq_norm_kernel(const float* __restrict__ emb,
                               float* __restrict__ out, long long out_size) {
    int k = blockIdx.x;
    int d = threadIdx.x;   // 256 threads, one per dim
    float v = emb[(size_t)k * DIM + d];
    float s = v * v;
    #pragma unroll
    for (int o = 16; o; o >>= 1) s += __shfl_xor_sync(0xFFFFFFFFu, s, o);
    __shared__ float ws[8];
    __shared__ float rs_sh;
    if ((d & 31) == 0) ws[d >> 5] = s;
    __syncthreads();
    if (d == 0) {
        float t = 0.f;
        #pragma unroll
        for (int i = 0; i < 8; i++) t += ws[i];
        float n = sqrtf(t);
        rs_sh = 1.0f / fmaxf(n, 1e-12f);
        if (k == 0 && out_size > (long long)QN) out[QN] = 0.0f;  // zero loss slot
    }
    __syncthreads();
    g_enT[(size_t)d * K_CODES + k] = v * rs_sh;
}

// ---------------------------------------------------------------------------
// Kernel B: fused GEMM (x · enT) + running argmax + gather + loss + writeback.
// 128x128 block tile, 8x8 microtile (split 4+4), 3-stage cp.async pipeline,
// one barrier per step.
// ---------------------------------------------------------------------------
__global__ void __launch_bounds__(THREADS, 1) vq_main_kernel(
    const float* __restrict__ x, const float* __restrict__ emb,
    float* __restrict__ out, long long out_size)
{
    extern __shared__ float smem[];
    float* xs = smem;                  // [DIM][TM]
    float* es = smem + XS_F;           // [NSTAGE][DC][TN]

    const int tid = threadIdx.x;
    const int tx4 = (tid & 15) << 2;   // col offset
    const int ty4 = (tid >> 4) << 2;   // row offset (ty in 0..15)

    const int n0 = blockIdx.x * TM;
    const int b  = n0 / T_LEN;
    const int tl = n0 % T_LEN;         // TM=128 divides T_LEN -> single batch
    const float* xb = x + (size_t)b * DIM * T_LEN + tl;

    const uint32_t es_base = (uint32_t)__cvta_generic_to_shared(es);

    // chunk s: dims [dc*DC, dc*DC+DC), codes [cc*TN, cc*TN+TN)
    auto load_chunk = [&](int s, int buf) {
        int cc = s >> 3, dc = s & 7;
        const float* src0 = g_enT + (size_t)(dc * DC) * K_CODES + cc * TN;
        uint32_t db = es_base + (uint32_t)buf * (EB_F * 4);
        #pragma unroll
        for (int i = 0; i < 4; i++) {
            int lin = i * THREADS + tid;       // 0..1023
            int kk  = lin >> 5;                // 0..31
            int c4  = (lin & 31) << 2;         // 0..124
            cp16(db + (uint32_t)(kk * TN + c4) * 4, src0 + (size_t)kk * K_CODES + c4);
        }
        cp_commit();
    };

    // Prologue: prefetch stages 0,1; load x tile (coalesced along t).
    load_chunk(0, 0);
    load_chunk(1, 1);
    #pragma unroll
    for (int i = 0; i < 32; i++) {
        int lin = i * THREADS + tid;           // 0..8191 float4s
        int d   = lin >> 5;
        int r4  = (lin & 31) << 2;
        float4 v = *(const float4*)(xb + (size_t)d * T_LEN + r4);
        *(float4*)(xs + d * TM + r4) = v;
    }

    float cmax[8], acc[8][8];
    int   cidx[8];
    #pragma unroll
    for (int i = 0; i < 8; i++) { cmax[i] = -1e30f; cidx[i] = 0; }

    int s = 0;
    #pragma unroll 1
    for (int cc = 0; cc < K_CODES / TN; ++cc) {
        #pragma unroll
        for (int i = 0; i < 8; i++)
            #pragma unroll
            for (int j = 0; j < 8; j++) acc[i][j] = 0.f;

        #pragma unroll 1
        for (int dc = 0; dc < DIM / DC; ++dc, ++s) {
            if (s >= NSTEPS - 1) cp_wait0(); else cp_wait1();
            __syncthreads();                       // stage s visible; stage (s+2)%3 free
            if (s + 2 < NSTEPS) {
                int nb = (s + 2) % NSTAGE;
                load_chunk(s + 2, nb);
            }
            const float* ebuf = es + (s % NSTAGE) * EB_F;
            const float* xss  = xs + dc * DC * TM;

            #pragma unroll 8
            for (int kk = 0; kk < DC; ++kk) {
                const float* ar = xss + kk * TM;
                const float* br = ebuf + kk * TN;
                float4 a0 = *(const float4*)(ar + ty4);
                float4 a1 = *(const float4*)(ar + 64 + ty4);
                float4 b0 = *(const float4*)(br + tx4);
                float4 b1 = *(const float4*)(br + 64 + tx4);
                float av[8] = {a0.x, a0.y, a0.z, a0.w, a1.x, a1.y, a1.z, a1.w};
                float bv[8] = {b0.x, b0.y, b0.z, b0.w, b1.x, b1.y, b1.z, b1.w};
                #pragma unroll
                for (int i = 0; i < 8; i++)
                    #pragma unroll
                    for (int j = 0; j < 8; j++)
                        acc[i][j] = fmaf(av[i], bv[j], acc[i][j]);
            }
        }

        // fold this code-chunk into running argmax (codes increasing per j)
        int cb0 = cc * TN + tx4;
        int cb1 = cc * TN + 64 + tx4;
        #pragma unroll
        for (int i = 0; i < 8; i++) {
            #pragma unroll
            for (int j = 0; j < 4; j++)
                if (acc[i][j] > cmax[i]) { cmax[i] = acc[i][j]; cidx[i] = cb0 + j; }
            #pragma unroll
            for (int j = 4; j < 8; j++)
                if (acc[i][j] > cmax[i]) { cmax[i] = acc[i][j]; cidx[i] = cb1 + (j - 4); }
        }
    }

    __syncthreads();   // protect es before reuse as scratch

    // ---- cross-thread argmax reduce (reuse es region as scratch) ----
    float* redv  = es;                         // [TM][16]
    int*   redi  = (int*)(es + TM * 16);       // [TM][16]
    int*   idx_s = (int*)(es + TM * 16 * 2);   // [TM]
    const int txi = tid & 15;
    #pragma unroll
    for (int i = 0; i < 8; i++) {
        int lr = (i < 4) ? (ty4 + i) : (64 + ty4 + (i - 4));
        redv[lr * 16 + txi] = cmax[i];
        redi[lr * 16 + txi] = cidx[i];
    }
    __syncthreads();
    if (tid < TM) {
        float bv = redv[tid * 16];
        int   bi = redi[tid * 16];
        #pragma unroll
        for (int j = 1; j < 16; j++) {
            float v  = redv[tid * 16 + j];
            int   ix = redi[tid * 16 + j];
            if (v > bv || (v == bv && ix < bi)) { bv = v; bi = ix; }
        }
        idx_s[tid] = bi;
        if (out_size >= (long long)(QN + 1 + N_ROWS))
            out[QN + 1 + n0 + tid] = (float)bi;   // indices as f32
    }
    __syncthreads();

    // ---- epilogue: gather embedding row, write [B,D,T] coalesced, loss ----
    const int r     = tid & 127;   // local row (t)
    const int dhalf = tid >> 7;    // which half of D
    const int myidx = idx_s[r];
    const float4* erow4 = (const float4*)(emb + (size_t)myidx * DIM + dhalf * 128);
    float* ob = out + (size_t)b * DIM * T_LEN + tl + r;
    float lsum = 0.f;
    #pragma unroll
    for (int dj = 0; dj < 32; ++dj) {
        float4 e4 = erow4[dj];
        int d = dhalf * 128 + dj * 4;
        float ev[4] = {e4.x, e4.y, e4.z, e4.w};
        #pragma unroll
        for (int i = 0; i < 4; i++) {
            float xv = xs[(d + i) * TM + r];
            float df = ev[i] - xv;
            lsum = fmaf(df, df, lsum);
            ob[(size_t)(d + i) * T_LEN] = ev[i];   // 32 consecutive t per warp
        }
    }

    // ---- loss block-reduce + single atomic per block ----
    #pragma unroll
    for (int o = 16; o; o >>= 1) lsum += __shfl_xor_sync(0xFFFFFFFFu, lsum, o);
    __shared__ float wsum[8];
    if ((tid & 31) == 0) wsum[tid >> 5] = lsum;
    __syncthreads();
    if (tid == 0) {
        float t = 0.f;
        #pragma unroll
        for (int i = 0; i < 8; i++) t += wsum[i];
        if (out_size > (long long)QN)
            atomicAdd(out + QN, t * (1.25f / 16777216.0f));
    }
}

// ---------------------------------------------------------------------------
extern "C" void kernel_launch(void* const* d_in, const int* in_sizes, int n_in,
                              void* d_out, int out_size) {
    const float* x   = (const float*)d_in[0];
    const float* emb = (const float*)d_in[1];
    if (n_in >= 2 && in_sizes[0] == K_CODES * DIM && in_sizes[1] == (int)QN) {
        const float* t = x; x = emb; emb = t;
    }
    float* out = (float*)d_out;

    const int smem_bytes = (XS_F + NSTAGE * EB_F) * 4;  // 180224
    cudaFuncSetAttribute(vq_main_kernel,
                         cudaFuncAttributeMaxDynamicSharedMemorySize, smem_bytes);

    vq_norm_kernel<<<K_CODES, 256>>>(emb, out, (long long)out_size);
    vq_main_kernel<<<N_ROWS / TM, THREADS, smem_bytes>>>(x, emb, out, (long long)out_size);
}

// round 4
// speedup vs baseline: 1.0363x; 1.0014x over previous
#include <cuda_runtime.h>
#include <cstdint>

#define K_CODES 1024
#define DIM     256
#define T_LEN   4096
#define B_SZ    16
#define N_ROWS  (B_SZ * T_LEN)                 // 65536
#define QN      ((size_t)B_SZ * DIM * T_LEN)   // 16777216

#define TM 128
#define TN 128
#define DC 32
#define NSTEPS ((K_CODES / TN) * (DIM / DC))   // 64
#define THREADS 256
#define XS_F (TM * DIM)          // 32768 floats (x tile, [d][row])
#define EB_F (DC * TN)           // 4096 floats per stage
#define NSTAGE 3

// Normalized embeddings, transposed to [D][K] so B-tiles stream coalesced.
__device__ float g_enT[DIM * K_CODES];

__device__ __forceinline__ void cp16(uint32_t dst, const void* src) {
    asm volatile("cp.async.cg.shared.global [%0], [%1], 16;\n" :: "r"(dst), "l"(src));
}
__device__ __forceinline__ void cp_commit() {
    asm volatile("cp.async.commit_group;\n");
}
__device__ __forceinline__ void cp_wait1() {
    asm volatile("cp.async.wait_group 1;\n");
}
__device__ __forceinline__ void cp_wait0() {
    asm volatile("cp.async.wait_group 0;\n");
}

// ---------------------------------------------------------------------------
// Kernel A: L2-normalize embeddings, write transposed g_enT[d*K + k].
// Also zeroes the loss slot in d_out.
// ---------------------------------------------------------------------------
__global__ void vq_norm_kernel(const float* __restrict__ emb,
                               float* __restrict__ out, long long out_size) {
    int k = blockIdx.x;
    int d = threadIdx.x;   // 256 threads, one per dim
    float v = emb[(size_t)k * DIM + d];
    float s = v * v;
    #pragma unroll
    for (int o = 16; o; o >>= 1) s += __shfl_xor_sync(0xFFFFFFFFu, s, o);
    __shared__ float ws[8];
    __shared__ float rs_sh;
    if ((d & 31) == 0) ws[d >> 5] = s;
    __syncthreads();
    if (d == 0) {
        float t = 0.f;
        #pragma unroll
        for (int i = 0; i < 8; i++) t += ws[i];
        float n = sqrtf(t);
        rs_sh = 1.0f / fmaxf(n, 1e-12f);
        if (k == 0 && out_size > (long long)QN) out[QN] = 0.0f;  // zero loss slot
    }
    __syncthreads();
    g_enT[(size_t)d * K_CODES + k] = v * rs_sh;
}

// ---------------------------------------------------------------------------
// Kernel B: fused GEMM (x · enT) + running argmax + gather + loss + writeback.
// 128x128 block tile, 8x8 microtile (split 4+4), 3-stage cp.async pipeline,
// one barrier per step.
// ---------------------------------------------------------------------------
__global__ void __launch_bounds__(THREADS, 1) vq_main_kernel(
    const float* __restrict__ x, const float* __restrict__ emb,
    float* __restrict__ out, long long out_size)
{
    extern __shared__ float smem[];
    float* xs = smem;                  // [DIM][TM]
    float* es = smem + XS_F;           // [NSTAGE][DC][TN]

    const int tid = threadIdx.x;
    const int tx4 = (tid & 15) << 2;   // col offset
    const int ty4 = (tid >> 4) << 2;   // row offset (ty in 0..15)

    const int n0 = blockIdx.x * TM;
    const int b  = n0 / T_LEN;
    const int tl = n0 % T_LEN;         // TM=128 divides T_LEN -> single batch
    const float* xb = x + (size_t)b * DIM * T_LEN + tl;

    const uint32_t es_base = (uint32_t)__cvta_generic_to_shared(es);

    // chunk s: dims [dc*DC, dc*DC+DC), codes [cc*TN, cc*TN+TN)
    auto load_chunk = [&](int s, int buf) {
        int cc = s >> 3, dc = s & 7;
        const float* src0 = g_enT + (size_t)(dc * DC) * K_CODES + cc * TN;
        uint32_t db = es_base + (uint32_t)buf * (EB_F * 4);
        #pragma unroll
        for (int i = 0; i < 4; i++) {
            int lin = i * THREADS + tid;       // 0..1023
            int kk  = lin >> 5;                // 0..31
            int c4  = (lin & 31) << 2;         // 0..124
            cp16(db + (uint32_t)(kk * TN + c4) * 4, src0 + (size_t)kk * K_CODES + c4);
        }
        cp_commit();
    };

    // Prologue: prefetch stages 0,1; load x tile (coalesced along t).
    load_chunk(0, 0);
    load_chunk(1, 1);
    #pragma unroll
    for (int i = 0; i < 32; i++) {
        int lin = i * THREADS + tid;           // 0..8191 float4s
        int d   = lin >> 5;
        int r4  = (lin & 31) << 2;
        float4 v = *(const float4*)(xb + (size_t)d * T_LEN + r4);
        *(float4*)(xs + d * TM + r4) = v;
    }

    float cmax[8], acc[8][8];
    int   cidx[8];
    #pragma unroll
    for (int i = 0; i < 8; i++) { cmax[i] = -1e30f; cidx[i] = 0; }

    int s = 0;
    #pragma unroll 1
    for (int cc = 0; cc < K_CODES / TN; ++cc) {
        #pragma unroll
        for (int i = 0; i < 8; i++)
            #pragma unroll
            for (int j = 0; j < 8; j++) acc[i][j] = 0.f;

        #pragma unroll 1
        for (int dc = 0; dc < DIM / DC; ++dc, ++s) {
            if (s >= NSTEPS - 1) cp_wait0(); else cp_wait1();
            __syncthreads();                       // stage s visible; stage (s+2)%3 free
            if (s + 2 < NSTEPS) {
                int nb = (s + 2) % NSTAGE;
                load_chunk(s + 2, nb);
            }
            const float* ebuf = es + (s % NSTAGE) * EB_F;
            const float* xss  = xs + dc * DC * TM;

            #pragma unroll 8
            for (int kk = 0; kk < DC; ++kk) {
                const float* ar = xss + kk * TM;
                const float* br = ebuf + kk * TN;
                float4 a0 = *(const float4*)(ar + ty4);
                float4 a1 = *(const float4*)(ar + 64 + ty4);
                float4 b0 = *(const float4*)(br + tx4);
                float4 b1 = *(const float4*)(br + 64 + tx4);
                float av[8] = {a0.x, a0.y, a0.z, a0.w, a1.x, a1.y, a1.z, a1.w};
                float bv[8] = {b0.x, b0.y, b0.z, b0.w, b1.x, b1.y, b1.z, b1.w};
                #pragma unroll
                for (int i = 0; i < 8; i++)
                    #pragma unroll
                    for (int j = 0; j < 8; j++)
                        acc[i][j] = fmaf(av[i], bv[j], acc[i][j]);
            }
        }

        // fold this code-chunk into running argmax (codes increasing per j)
        int cb0 = cc * TN + tx4;
        int cb1 = cc * TN + 64 + tx4;
        #pragma unroll
        for (int i = 0; i < 8; i++) {
            #pragma unroll
            for (int j = 0; j < 4; j++)
                if (acc[i][j] > cmax[i]) { cmax[i] = acc[i][j]; cidx[i] = cb0 + j; }
            #pragma unroll
            for (int j = 4; j < 8; j++)
                if (acc[i][j] > cmax[i]) { cmax[i] = acc[i][j]; cidx[i] = cb1 + (j - 4); }
        }
    }

    __syncthreads();   // protect es before reuse as scratch

    // ---- cross-thread argmax reduce (reuse es region as scratch) ----
    float* redv  = es;                         // [TM][16]
    int*   redi  = (int*)(es + TM * 16);       // [TM][16]
    int*   idx_s = (int*)(es + TM * 16 * 2);   // [TM]
    const int txi = tid & 15;
    #pragma unroll
    for (int i = 0; i < 8; i++) {
        int lr = (i < 4) ? (ty4 + i) : (64 + ty4 + (i - 4));
        redv[lr * 16 + txi] = cmax[i];
        redi[lr * 16 + txi] = cidx[i];
    }
    __syncthreads();
    if (tid < TM) {
        float bv = redv[tid * 16];
        int   bi = redi[tid * 16];
        #pragma unroll
        for (int j = 1; j < 16; j++) {
            float v  = redv[tid * 16 + j];
            int   ix = redi[tid * 16 + j];
            if (v > bv || (v == bv && ix < bi)) { bv = v; bi = ix; }
        }
        idx_s[tid] = bi;
        if (out_size >= (long long)(QN + 1 + N_ROWS))
            out[QN + 1 + n0 + tid] = (float)bi;   // indices as f32
    }
    __syncthreads();

    // ---- epilogue: gather embedding row, write [B,D,T] coalesced, loss ----
    const int r     = tid & 127;   // local row (t)
    const int dhalf = tid >> 7;    // which half of D
    const int myidx = idx_s[r];
    const float4* erow4 = (const float4*)(emb + (size_t)myidx * DIM + dhalf * 128);
    float* ob = out + (size_t)b * DIM * T_LEN + tl + r;
    float lsum = 0.f;
    #pragma unroll
    for (int dj = 0; dj < 32; ++dj) {
        float4 e4 = erow4[dj];
        int d = dhalf * 128 + dj * 4;
        float ev[4] = {e4.x, e4.y, e4.z, e4.w};
        #pragma unroll
        for (int i = 0; i < 4; i++) {
            float xv = xs[(d + i) * TM + r];
            float df = ev[i] - xv;
            lsum = fmaf(df, df, lsum);
            ob[(size_t)(d + i) * T_LEN] = ev[i];   // 32 consecutive t per warp
        }
    }

    // ---- loss block-reduce + single atomic per block ----
    #pragma unroll
    for (int o = 16; o; o >>= 1) lsum += __shfl_xor_sync(0xFFFFFFFFu, lsum, o);
    __shared__ float wsum[8];
    if ((tid & 31) == 0) wsum[tid >> 5] = lsum;
    __syncthreads();
    if (tid == 0) {
        float t = 0.f;
        #pragma unroll
        for (int i = 0; i < 8; i++) t += wsum[i];
        if (out_size > (long long)QN)
            atomicAdd(out + QN, t * (1.25f / 16777216.0f));
    }
}

// ---------------------------------------------------------------------------
extern "C" void kernel_launch(void* const* d_in, const int* in_sizes, int n_in,
                              void* d_out, int out_size) {
    const float* x   = (const float*)d_in[0];
    const float* emb = (const float*)d_in[1];
    if (n_in >= 2 && in_sizes[0] == K_CODES * DIM && in_sizes[1] == (int)QN) {
        const float* t = x; x = emb; emb = t;
    }
    float* out = (float*)d_out;

    const int smem_bytes = (XS_F + NSTAGE * EB_F) * 4;  // 180224
    cudaFuncSetAttribute(vq_main_kernel,
                         cudaFuncAttributeMaxDynamicSharedMemorySize, smem_bytes);

    vq_norm_kernel<<<K_CODES, 256>>>(emb, out, (long long)out_size);
    vq_main_kernel<<<N_ROWS / TM, THREADS, smem_bytes>>>(x, emb, out, (long long)out_size);
}